// round 3
// baseline (speedup 1.0000x reference)
#include <cuda_runtime.h>

#define N_NODES 100000
#define D 64
// float4 lanes per node row
#define L4 16

// Scratch (allocation-free rule: __device__ globals). 16B-aligned for float4 atomics.
__device__ __align__(16) float g_h [N_NODES * D];   // gemm output per layer
__device__ __align__(16) float g_t0[N_NODES * D];   // layer0 output
__device__ __align__(16) float g_t1[N_NODES * D];   // layer1 output
__device__ int   g_deg[N_NODES];
__device__ float g_dinv[N_NODES];

__global__ void k_zero_deg(int n) {
    int i = blockIdx.x * blockDim.x + threadIdx.x;
    if (i < n) g_deg[i] = 0;
}

__global__ void k_count_deg(const int* __restrict__ dst, int e) {
    int i = blockIdx.x * blockDim.x + threadIdx.x;
    if (i < e) atomicAdd(&g_deg[dst[i]], 1);
}

__global__ void k_dinv(int n) {
    int i = blockIdx.x * blockDim.x + threadIdx.x;
    if (i < n) g_dinv[i] = rsqrtf((float)g_deg[i] + 1.0f);
}

// H[n,64] = (RELU? max(A,0):A) @ W[64,64]
// 256 threads/block, 64 rows/block; thread tid handles row tid>>2,
// 16 output cols starting at (tid&3)*16. W staged in smem.
template<bool RELU>
__global__ void __launch_bounds__(256) k_gemm(const float* __restrict__ A,
                                              const float* __restrict__ W,
                                              float* __restrict__ H, int n) {
    __shared__ float4 Ws[1024];  // 64x64 floats
    int tid = threadIdx.x;
    const float4* W4 = (const float4*)W;
    #pragma unroll
    for (int i = 0; i < 4; i++) Ws[tid + i * 256] = W4[tid + i * 256];
    __syncthreads();

    int row = blockIdx.x * 64 + (tid >> 2);
    if (row >= n) return;
    int cseg4 = (tid & 3) * 4;  // float4-index of first output col group

    float acc[16];
    #pragma unroll
    for (int c = 0; c < 16; c++) acc[c] = 0.0f;

    const float4* a4 = (const float4*)(A + (size_t)row * D);
    #pragma unroll
    for (int k4 = 0; k4 < 16; k4++) {
        float4 a = a4[k4];
        if (RELU) {
            a.x = fmaxf(a.x, 0.0f); a.y = fmaxf(a.y, 0.0f);
            a.z = fmaxf(a.z, 0.0f); a.w = fmaxf(a.w, 0.0f);
        }
        const float* ap = &a.x;
        #pragma unroll
        for (int j = 0; j < 4; j++) {
            float av = ap[j];
            int k = k4 * 4 + j;
            #pragma unroll
            for (int c4 = 0; c4 < 4; c4++) {
                float4 w = Ws[k * 16 + cseg4 + c4];
                acc[c4 * 4 + 0] += av * w.x;
                acc[c4 * 4 + 1] += av * w.y;
                acc[c4 * 4 + 2] += av * w.z;
                acc[c4 * 4 + 3] += av * w.w;
            }
        }
    }
    float4* h4 = (float4*)(H + (size_t)row * D) + cseg4;
    #pragma unroll
    for (int c4 = 0; c4 < 4; c4++)
        h4[c4] = make_float4(acc[c4 * 4 + 0], acc[c4 * 4 + 1],
                             acc[c4 * 4 + 2], acc[c4 * 4 + 3]);
}

// out = h * dinv[node]^2 + b   (self-loop term; also zero-inits atomic target)
__global__ void k_init(const float* __restrict__ H, const float* __restrict__ b,
                       float* __restrict__ out, int n) {
    int idx = blockIdx.x * blockDim.x + threadIdx.x;
    if (idx >= n * L4) return;
    int node = idx >> 4;
    int c4   = idx & 15;
    float di = g_dinv[node];
    float s  = di * di;
    float4 h  = ((const float4*)H)[idx];
    float4 bb = ((const float4*)b)[c4];
    ((float4*)out)[idx] = make_float4(h.x * s + bb.x, h.y * s + bb.y,
                                      h.z * s + bb.z, h.w * s + bb.w);
}

// Per edge: out[dst] += h[src] * dinv[src]*dinv[dst]
// 16 threads per edge, one float4 each, vector atomicAdd (sm_90+ RED.128)
__global__ void k_scatter(const float* __restrict__ H,
                          const int* __restrict__ src,
                          const int* __restrict__ dst,
                          float* __restrict__ out, int e) {
    int t = blockIdx.x * blockDim.x + threadIdx.x;
    int edge = t >> 4;
    if (edge >= e) return;
    int l = t & 15;
    int s = __ldg(&src[edge]);
    int d = __ldg(&dst[edge]);
    float nrm = g_dinv[s] * g_dinv[d];
    float4 v = ((const float4*)H)[(size_t)s * L4 + l];
    v.x *= nrm; v.y *= nrm; v.z *= nrm; v.w *= nrm;
#if __CUDA_ARCH__ >= 900
    atomicAdd((float4*)out + (size_t)d * L4 + l, v);
#else
    float* p = out + (size_t)d * D + l * 4;
    atomicAdd(p + 0, v.x); atomicAdd(p + 1, v.y);
    atomicAdd(p + 2, v.z); atomicAdd(p + 3, v.w);
#endif
}

extern "C" void kernel_launch(void* const* d_in, const int* in_sizes, int n_in,
                              void* d_out, int out_size) {
    const float* x  = (const float*)d_in[0];
    const int*   ei = (const int*)d_in[1];   // int32: JAX x64-disabled downcasts int64
    const float* W0 = (const float*)d_in[2];
    const float* b0 = (const float*)d_in[3];
    const float* W1 = (const float*)d_in[4];
    const float* b1 = (const float*)d_in[5];
    const float* W2 = (const float*)d_in[6];
    const float* b2 = (const float*)d_in[7];
    float* out = (float*)d_out;

    int n = in_sizes[0] / D;
    int e = in_sizes[1] / 2;
    const int* src = ei;
    const int* dst = ei + e;

    float *h, *t0, *t1;
    cudaGetSymbolAddress((void**)&h,  g_h);
    cudaGetSymbolAddress((void**)&t0, g_t0);
    cudaGetSymbolAddress((void**)&t1, g_t1);

    const int TB = 256;
    long long nd = (long long)n * L4;
    long long ed = (long long)e * L4;
    int gb_n    = (n + TB - 1) / TB;
    int gb_e    = (e + TB - 1) / TB;
    int gb_gemm = (n + 63) / 64;
    int gb_nd   = (int)((nd + TB - 1) / TB);
    int gb_sc   = (int)((ed + TB - 1) / TB);

    // degree / normalization (recomputed every call: deterministic, graph-safe)
    k_zero_deg<<<gb_n, TB>>>(n);
    k_count_deg<<<gb_e, TB>>>(dst, e);
    k_dinv<<<gb_n, TB>>>(n);

    // layer 0: h = x @ W0 ; t0 = h*dinv^2 + b0 ; scatter into t0
    k_gemm<false><<<gb_gemm, TB>>>(x, W0, h, n);
    k_init<<<gb_nd, TB>>>(h, b0, t0, n);
    k_scatter<<<gb_sc, TB>>>(h, src, dst, t0, e);

    // layer 1: h = relu(t0) @ W1 ; t1 = h*dinv^2 + b1 ; scatter into t1
    k_gemm<true><<<gb_gemm, TB>>>(t0, W1, h, n);
    k_init<<<gb_nd, TB>>>(h, b1, t1, n);
    k_scatter<<<gb_sc, TB>>>(h, src, dst, t1, e);

    // layer 2 (no relu on output): h = relu(t1) @ W2 ; out = h*dinv^2 + b2 ; scatter into out
    k_gemm<true><<<gb_gemm, TB>>>(t1, W2, h, n);
    k_init<<<gb_nd, TB>>>(h, b2, out, n);
    k_scatter<<<gb_sc, TB>>>(h, src, dst, out, e);
}

// round 5
// speedup vs baseline: 1.4246x; 1.4246x over previous
#include <cuda_runtime.h>

#define N_NODES 100000
#define D 64
#define L4 16

// Scratch (allocation-free rule). 16B-aligned for float4 atomics.
__device__ __align__(16) float g_h [N_NODES * D];
__device__ __align__(16) float g_t0[N_NODES * D];
__device__ __align__(16) float g_t1[N_NODES * D];
__device__ int   g_deg[N_NODES];
__device__ float g_dinv[N_NODES];

__global__ void k_zero_deg(int n) {
    int i = blockIdx.x * blockDim.x + threadIdx.x;
    if (i < n) g_deg[i] = 0;
}

__global__ void k_count_deg(const int* __restrict__ dst, int e) {
    int i = blockIdx.x * blockDim.x + threadIdx.x;
    if (i < e) atomicAdd(&g_deg[dst[i]], 1);
}

__global__ void k_dinv(int n) {
    int i = blockIdx.x * blockDim.x + threadIdx.x;
    if (i < n) g_dinv[i] = rsqrtf((float)g_deg[i] + 1.0f);
}

// Fused: H = (RELU? relu(A):A) @ W ;  OUT = H*dinv^2 + b
// 256 threads/block, 256 rows/block. Thread: 4 consecutive rows x 16 cols.
// Register blocking: each LDS.128 of W feeds 16 FFMAs.
template<bool RELU>
__global__ void __launch_bounds__(256, 2) k_gemm_fused(
        const float* __restrict__ A, const float* __restrict__ W,
        const float* __restrict__ b, float* __restrict__ H,
        float* __restrict__ OUT, int n) {
    __shared__ float4 Ws[1024];   // 64x64 W
    __shared__ float4 bs[16];     // bias
    int tid = threadIdx.x;
    const float4* W4 = (const float4*)W;
    #pragma unroll
    for (int i = 0; i < 4; i++) Ws[tid + i * 256] = W4[tid + i * 256];
    if (tid < 16) bs[tid] = ((const float4*)b)[tid];
    __syncthreads();

    int row0 = blockIdx.x * 256 + (tid >> 2) * 4;   // 4 consecutive rows
    int cs   = (tid & 3) * 4;                        // first float4-col of 16-col slice

    // Precompute clamped row pointers (hoisted out of k-loop)
    const float4* Ar[4];
    #pragma unroll
    for (int rr = 0; rr < 4; rr++) {
        int r = row0 + rr; if (r >= n) r = n - 1;   // clamp; stores are guarded
        Ar[rr] = (const float4*)A + (size_t)r * 16;
    }

    float acc[4][16];
    #pragma unroll
    for (int r = 0; r < 4; r++)
        #pragma unroll
        for (int c = 0; c < 16; c++) acc[r][c] = 0.0f;

    #pragma unroll
    for (int k4 = 0; k4 < 16; k4++) {
        float4 a[4];
        #pragma unroll
        for (int rr = 0; rr < 4; rr++) {
            a[rr] = Ar[rr][k4];
            if (RELU) {
                a[rr].x = fmaxf(a[rr].x, 0.0f); a[rr].y = fmaxf(a[rr].y, 0.0f);
                a[rr].z = fmaxf(a[rr].z, 0.0f); a[rr].w = fmaxf(a[rr].w, 0.0f);
            }
        }
        #pragma unroll
        for (int j = 0; j < 4; j++) {
            int k = k4 * 4 + j;
            #pragma unroll
            for (int c4 = 0; c4 < 4; c4++) {
                float4 w = Ws[k * 16 + cs + c4];
                #pragma unroll
                for (int rr = 0; rr < 4; rr++) {
                    float av = (&a[rr].x)[j];
                    acc[rr][c4 * 4 + 0] += av * w.x;
                    acc[rr][c4 * 4 + 1] += av * w.y;
                    acc[rr][c4 * 4 + 2] += av * w.z;
                    acc[rr][c4 * 4 + 3] += av * w.w;
                }
            }
        }
    }

    #pragma unroll
    for (int rr = 0; rr < 4; rr++) {
        int r = row0 + rr;
        if (r >= n) break;
        float di = g_dinv[r];
        float s = di * di;
        float4* h4 = (float4*)(H   + (size_t)r * D) + cs;
        float4* o4 = (float4*)(OUT + (size_t)r * D) + cs;
        #pragma unroll
        for (int c4 = 0; c4 < 4; c4++) {
            float4 v = make_float4(acc[rr][c4*4+0], acc[rr][c4*4+1],
                                   acc[rr][c4*4+2], acc[rr][c4*4+3]);
            h4[c4] = v;
            float4 bb = bs[cs + c4];
            o4[c4] = make_float4(v.x * s + bb.x, v.y * s + bb.y,
                                 v.z * s + bb.z, v.w * s + bb.w);
        }
    }
}

// Per edge: out[dst] += h[src] * dinv[src]*dinv[dst]
// 16 threads/edge, one float4 each, vector atomicAdd (RED.128)
__global__ void k_scatter(const float* __restrict__ H,
                          const int* __restrict__ src,
                          const int* __restrict__ dst,
                          float* __restrict__ out, int e) {
    int t = blockIdx.x * blockDim.x + threadIdx.x;
    int edge = t >> 4;
    if (edge >= e) return;
    int l = t & 15;
    int s = __ldg(&src[edge]);
    int d = __ldg(&dst[edge]);
    float nrm = g_dinv[s] * g_dinv[d];
    float4 v = ((const float4*)H)[(size_t)s * L4 + l];
    v.x *= nrm; v.y *= nrm; v.z *= nrm; v.w *= nrm;
#if __CUDA_ARCH__ >= 900
    atomicAdd((float4*)out + (size_t)d * L4 + l, v);
#else
    float* p = out + (size_t)d * D + l * 4;
    atomicAdd(p + 0, v.x); atomicAdd(p + 1, v.y);
    atomicAdd(p + 2, v.z); atomicAdd(p + 3, v.w);
#endif
}

extern "C" void kernel_launch(void* const* d_in, const int* in_sizes, int n_in,
                              void* d_out, int out_size) {
    const float* x  = (const float*)d_in[0];
    const int*   ei = (const int*)d_in[1];   // int32 (JAX x64-disabled)
    const float* W0 = (const float*)d_in[2];
    const float* b0 = (const float*)d_in[3];
    const float* W1 = (const float*)d_in[4];
    const float* b1 = (const float*)d_in[5];
    const float* W2 = (const float*)d_in[6];
    const float* b2 = (const float*)d_in[7];
    float* out = (float*)d_out;

    int n = in_sizes[0] / D;
    int e = in_sizes[1] / 2;
    const int* src = ei;
    const int* dst = ei + e;

    float *h, *t0, *t1;
    cudaGetSymbolAddress((void**)&h,  g_h);
    cudaGetSymbolAddress((void**)&t0, g_t0);
    cudaGetSymbolAddress((void**)&t1, g_t1);

    const int TB = 256;
    int gb_n    = (n + TB - 1) / TB;
    int gb_e    = (e + TB - 1) / TB;
    int gb_gemm = (n + 255) / 256;
    long long ed = (long long)e * L4;
    int gb_sc   = (int)((ed + TB - 1) / TB);

    k_zero_deg<<<gb_n, TB>>>(n);
    k_count_deg<<<gb_e, TB>>>(dst, e);
    k_dinv<<<gb_n, TB>>>(n);

    // layer 0
    k_gemm_fused<false><<<gb_gemm, TB>>>(x, W0, b0, h, t0, n);
    k_scatter<<<gb_sc, TB>>>(h, src, dst, t0, e);
    // layer 1
    k_gemm_fused<true><<<gb_gemm, TB>>>(t0, W1, b1, h, t1, n);
    k_scatter<<<gb_sc, TB>>>(h, src, dst, t1, e);
    // layer 2
    k_gemm_fused<true><<<gb_gemm, TB>>>(t1, W2, b2, h, out, n);
    k_scatter<<<gb_sc, TB>>>(h, src, dst, out, e);
}

// round 8
// speedup vs baseline: 2.0557x; 1.4430x over previous
#include <cuda_runtime.h>

#define N_NODES 100000
#define MAX_E   1600000
#define D 64
#define L4 16
#define SCAN_B 1024

struct Edge { int s; float nrm; };

// Scratch (allocation-free rule). 16B-aligned where float4-accessed.
__device__ __align__(16) float g_h [N_NODES * D];
__device__ __align__(16) float g_t0[N_NODES * D];
__device__ __align__(16) float g_t1[N_NODES * D];
__device__ int   g_deg [N_NODES];
__device__ int   g_fill[N_NODES];
__device__ int   g_rowp[N_NODES];
__device__ float g_dinv[N_NODES];
__device__ int   g_bsum[256];
__device__ __align__(8) Edge g_csr[MAX_E];

__global__ void k_zero(int n) {
    int i = blockIdx.x * blockDim.x + threadIdx.x;
    if (i < n) { g_deg[i] = 0; g_fill[i] = 0; }
}

__global__ void k_count_deg(const int* __restrict__ dst, int e) {
    int i = blockIdx.x * blockDim.x + threadIdx.x;
    if (i < e) atomicAdd(&g_deg[dst[i]], 1);
}

__global__ void k_dinv(int n) {
    int i = blockIdx.x * blockDim.x + threadIdx.x;
    if (i < n) g_dinv[i] = rsqrtf((float)g_deg[i] + 1.0f);
}

// ---- exclusive scan of g_deg -> g_rowp (3 steps) ----
__global__ void k_scan_block(int n) {
    __shared__ int sm[SCAN_B];
    int t = threadIdx.x;
    int i = blockIdx.x * SCAN_B + t;
    int v = (i < n) ? g_deg[i] : 0;
    sm[t] = v;
    __syncthreads();
    #pragma unroll
    for (int off = 1; off < SCAN_B; off <<= 1) {
        int add = (t >= off) ? sm[t - off] : 0;
        __syncthreads();
        sm[t] += add;
        __syncthreads();
    }
    if (i < n) g_rowp[i] = sm[t] - v;            // exclusive within block
    if (t == SCAN_B - 1) g_bsum[blockIdx.x] = sm[t];
}

__global__ void k_scan_bsum(int nb) {
    if (nb > 256) nb = 256;
    int acc = 0;
    for (int b = 0; b < nb; b++) { int v = g_bsum[b]; g_bsum[b] = acc; acc += v; }
}

__global__ void k_scan_add(int n) {
    int i = blockIdx.x * blockDim.x + threadIdx.x;
    if (i < n) g_rowp[i] += g_bsum[i / SCAN_B];
}

// ---- CSR fill: csr[pos] = {src, dinv[src]*dinv[dst]} ----
__global__ void k_fill(const int* __restrict__ src, const int* __restrict__ dst, int e) {
    int i = blockIdx.x * blockDim.x + threadIdx.x;
    if (i >= e) return;
    int s = src[i], d = dst[i];
    int pos = g_rowp[d] + atomicAdd(&g_fill[d], 1);
    if (pos >= MAX_E) pos = MAX_E - 1;           // defensive clamp (unreachable)
    Edge ed; ed.s = s; ed.nrm = g_dinv[s] * g_dinv[d];
    g_csr[pos] = ed;
}

// Fused: H = (RELU? relu(A):A) @ W ;  OUT = H*dinv^2 + b
template<bool RELU>
__global__ void __launch_bounds__(256, 2) k_gemm_fused(
        const float* __restrict__ A, const float* __restrict__ W,
        const float* __restrict__ b, float* __restrict__ H,
        float* __restrict__ OUT, int n) {
    __shared__ float4 Ws[1024];
    __shared__ float4 bs[16];
    int tid = threadIdx.x;
    const float4* W4 = (const float4*)W;
    #pragma unroll
    for (int i = 0; i < 4; i++) Ws[tid + i * 256] = W4[tid + i * 256];
    if (tid < 16) bs[tid] = ((const float4*)b)[tid];
    __syncthreads();

    int row0 = blockIdx.x * 256 + (tid >> 2) * 4;
    int cs   = (tid & 3) * 4;

    const float4* Ar[4];
    #pragma unroll
    for (int rr = 0; rr < 4; rr++) {
        int r = row0 + rr; if (r >= n) r = n - 1;
        Ar[rr] = (const float4*)A + (size_t)r * 16;
    }

    float acc[4][16];
    #pragma unroll
    for (int r = 0; r < 4; r++)
        #pragma unroll
        for (int c = 0; c < 16; c++) acc[r][c] = 0.0f;

    #pragma unroll
    for (int k4 = 0; k4 < 16; k4++) {
        float4 a[4];
        #pragma unroll
        for (int rr = 0; rr < 4; rr++) {
            a[rr] = Ar[rr][k4];
            if (RELU) {
                a[rr].x = fmaxf(a[rr].x, 0.0f); a[rr].y = fmaxf(a[rr].y, 0.0f);
                a[rr].z = fmaxf(a[rr].z, 0.0f); a[rr].w = fmaxf(a[rr].w, 0.0f);
            }
        }
        #pragma unroll
        for (int j = 0; j < 4; j++) {
            int k = k4 * 4 + j;
            #pragma unroll
            for (int c4 = 0; c4 < 4; c4++) {
                float4 w = Ws[k * 16 + cs + c4];
                #pragma unroll
                for (int rr = 0; rr < 4; rr++) {
                    float av = (&a[rr].x)[j];
                    acc[rr][c4 * 4 + 0] += av * w.x;
                    acc[rr][c4 * 4 + 1] += av * w.y;
                    acc[rr][c4 * 4 + 2] += av * w.z;
                    acc[rr][c4 * 4 + 3] += av * w.w;
                }
            }
        }
    }

    #pragma unroll
    for (int rr = 0; rr < 4; rr++) {
        int r = row0 + rr;
        if (r >= n) break;
        float di = g_dinv[r];
        float s = di * di;
        float4* h4 = (float4*)(H   + (size_t)r * D) + cs;
        float4* o4 = (float4*)(OUT + (size_t)r * D) + cs;
        #pragma unroll
        for (int c4 = 0; c4 < 4; c4++) {
            float4 v = make_float4(acc[rr][c4*4+0], acc[rr][c4*4+1],
                                   acc[rr][c4*4+2], acc[rr][c4*4+3]);
            h4[c4] = v;
            float4 bb = bs[cs + c4];
            o4[c4] = make_float4(v.x * s + bb.x, v.y * s + bb.y,
                                 v.z * s + bb.z, v.w * s + bb.w);
        }
    }
}

// CSR gather: 16 threads per dst node, lane l owns float4 column l.
// out[node] += sum_e h[csr[e].s] * csr[e].nrm   (non-atomic RMW)
__global__ void __launch_bounds__(256) k_gather(const float* __restrict__ H,
                                                float* __restrict__ out, int n) {
    int t = blockIdx.x * blockDim.x + threadIdx.x;
    int node = t >> 4;
    if (node >= n) return;
    int l = t & 15;

    int start = __ldg(&g_rowp[node]);
    int cnt   = __ldg(&g_deg[node]);
    const Edge* ce = g_csr + start;
    float4 acc = make_float4(0.f, 0.f, 0.f, 0.f);

    if (cnt > 0) {
        Edge nxt = ce[0];
        for (int j = 0; j < cnt; j++) {
            Edge cur = nxt;
            if (j + 1 < cnt) nxt = ce[j + 1];
            float4 v = ((const float4*)H)[(size_t)cur.s * L4 + l];
            acc.x += v.x * cur.nrm; acc.y += v.y * cur.nrm;
            acc.z += v.z * cur.nrm; acc.w += v.w * cur.nrm;
        }
        float4* o = (float4*)out + (size_t)node * L4 + l;
        float4 ov = *o;
        ov.x += acc.x; ov.y += acc.y; ov.z += acc.z; ov.w += acc.w;
        *o = ov;
    }
}

extern "C" void kernel_launch(void* const* d_in, const int* in_sizes, int n_in,
                              void* d_out, int out_size) {
    const float* x  = (const float*)d_in[0];
    const int*   ei = (const int*)d_in[1];   // int32 (JAX x64-disabled)
    const float* W0 = (const float*)d_in[2];
    const float* b0 = (const float*)d_in[3];
    const float* W1 = (const float*)d_in[4];
    const float* b1 = (const float*)d_in[5];
    const float* W2 = (const float*)d_in[6];
    const float* b2 = (const float*)d_in[7];
    float* out = (float*)d_out;

    int n = in_sizes[0] / D;
    int e = in_sizes[1] / 2;
    const int* src = ei;
    const int* dst = ei + e;

    float *h, *t0, *t1;
    cudaGetSymbolAddress((void**)&h,  g_h);
    cudaGetSymbolAddress((void**)&t0, g_t0);
    cudaGetSymbolAddress((void**)&t1, g_t1);

    const int TB = 256;
    int gb_n    = (n + TB - 1) / TB;
    int gb_e    = (e + TB - 1) / TB;
    int gb_gemm = (n + 255) / 256;
    int nb_scan = (n + SCAN_B - 1) / SCAN_B;
    long long nl = (long long)n * L4;
    int gb_ga   = (int)((nl + TB - 1) / TB);

    // CSR build (once per launch, reused by 3 layers)
    k_zero<<<gb_n, TB>>>(n);
    k_count_deg<<<gb_e, TB>>>(dst, e);
    k_dinv<<<gb_n, TB>>>(n);
    k_scan_block<<<nb_scan, SCAN_B>>>(n);
    k_scan_bsum<<<1, 1>>>(nb_scan);
    k_scan_add<<<gb_n, TB>>>(n);
    k_fill<<<gb_e, TB>>>(src, dst, e);

    // layer 0
    k_gemm_fused<false><<<gb_gemm, TB>>>(x, W0, b0, h, t0, n);
    k_gather<<<gb_ga, TB>>>(h, t0, n);
    // layer 1
    k_gemm_fused<true><<<gb_gemm, TB>>>(t0, W1, b1, h, t1, n);
    k_gather<<<gb_ga, TB>>>(h, t1, n);
    // layer 2
    k_gemm_fused<true><<<gb_gemm, TB>>>(t1, W2, b2, h, out, n);
    k_gather<<<gb_ga, TB>>>(h, out, n);
}

// round 9
// speedup vs baseline: 2.4017x; 1.1683x over previous
#include <cuda_runtime.h>
#include <cuda_fp16.h>

#define N_NODES 100000
#define MAX_E   1600000
#define D 64
#define SCAN_B 1024

struct Edge { int s; float nrm; };

// Scratch (allocation-free rule).
__device__ __align__(256) __half g_hh[N_NODES * D];   // fp16 gemm output (gather source)
__device__ __align__(256) float  g_t0[N_NODES * D];
__device__ __align__(256) float  g_t1[N_NODES * D];
__device__ int   g_deg [N_NODES];
__device__ int   g_fill[N_NODES];
__device__ int   g_rowp[N_NODES];
__device__ float g_dinv[N_NODES];
__device__ int   g_bsum[256];
__device__ __align__(8) Edge g_csr[MAX_E];

__global__ void k_zero(int n) {
    int i = blockIdx.x * blockDim.x + threadIdx.x;
    if (i < n) { g_deg[i] = 0; g_fill[i] = 0; }
}

__global__ void k_count_deg(const int* __restrict__ dst, int e) {
    int i = blockIdx.x * blockDim.x + threadIdx.x;
    if (i < e) atomicAdd(&g_deg[dst[i]], 1);
}

__global__ void k_dinv(int n) {
    int i = blockIdx.x * blockDim.x + threadIdx.x;
    if (i < n) g_dinv[i] = rsqrtf((float)g_deg[i] + 1.0f);
}

// ---- exclusive scan of g_deg -> g_rowp ----
__global__ void k_scan_block(int n) {
    __shared__ int sm[SCAN_B];
    int t = threadIdx.x;
    int i = blockIdx.x * SCAN_B + t;
    int v = (i < n) ? g_deg[i] : 0;
    sm[t] = v;
    __syncthreads();
    #pragma unroll
    for (int off = 1; off < SCAN_B; off <<= 1) {
        int add = (t >= off) ? sm[t - off] : 0;
        __syncthreads();
        sm[t] += add;
        __syncthreads();
    }
    if (i < n) g_rowp[i] = sm[t] - v;
    if (t == SCAN_B - 1) g_bsum[blockIdx.x] = sm[t];
}

__global__ void k_scan_bsum(int nb) {
    if (nb > 256) nb = 256;
    int acc = 0;
    for (int b = 0; b < nb; b++) { int v = g_bsum[b]; g_bsum[b] = acc; acc += v; }
}

__global__ void k_scan_add(int n) {
    int i = blockIdx.x * blockDim.x + threadIdx.x;
    if (i < n) g_rowp[i] += g_bsum[i / SCAN_B];
}

__global__ void k_fill(const int* __restrict__ src, const int* __restrict__ dst, int e) {
    int i = blockIdx.x * blockDim.x + threadIdx.x;
    if (i >= e) return;
    int s = src[i], d = dst[i];
    int pos = g_rowp[d] + atomicAdd(&g_fill[d], 1);
    if (pos >= MAX_E) pos = MAX_E - 1;
    Edge ed; ed.s = s; ed.nrm = g_dinv[s] * g_dinv[d];
    g_csr[pos] = ed;
}

// Fused: H(fp16) = (RELU? relu(A):A) @ W ;  OUT(fp32) = H*dinv^2 + b
// 256 threads/block, 128 rows/block. Thread: 4 rows x 8 cols (32 acc regs).
template<bool RELU>
__global__ void __launch_bounds__(256, 3) k_gemm_fused(
        const float* __restrict__ A, const float* __restrict__ W,
        const float* __restrict__ b, __half* __restrict__ Hh,
        float* __restrict__ OUT, int n) {
    __shared__ float4 Ws[1024];   // 64x64 W
    __shared__ float4 bs[16];
    int tid = threadIdx.x;
    const float4* W4 = (const float4*)W;
    #pragma unroll
    for (int i = 0; i < 4; i++) Ws[tid + i * 256] = W4[tid + i * 256];
    if (tid < 16) bs[tid] = ((const float4*)b)[tid];
    __syncthreads();

    int cslice = tid & 7;                       // 8 col-slices of 8 cols
    int row0   = blockIdx.x * 128 + (tid >> 3) * 4;
    int c2     = cslice * 2;                    // first float4-col index

    const float4* Ar[4];
    #pragma unroll
    for (int rr = 0; rr < 4; rr++) {
        int r = row0 + rr; if (r >= n) r = n - 1;
        Ar[rr] = (const float4*)A + (size_t)r * 16;
    }

    float acc[4][8];
    #pragma unroll
    for (int r = 0; r < 4; r++)
        #pragma unroll
        for (int c = 0; c < 8; c++) acc[r][c] = 0.0f;

    #pragma unroll
    for (int k4 = 0; k4 < 16; k4++) {
        float4 a[4];
        #pragma unroll
        for (int rr = 0; rr < 4; rr++) {
            a[rr] = Ar[rr][k4];
            if (RELU) {
                a[rr].x = fmaxf(a[rr].x, 0.0f); a[rr].y = fmaxf(a[rr].y, 0.0f);
                a[rr].z = fmaxf(a[rr].z, 0.0f); a[rr].w = fmaxf(a[rr].w, 0.0f);
            }
        }
        #pragma unroll
        for (int j = 0; j < 4; j++) {
            int k = k4 * 4 + j;
            float4 w0 = Ws[k * 16 + c2];
            float4 w1 = Ws[k * 16 + c2 + 1];
            #pragma unroll
            for (int rr = 0; rr < 4; rr++) {
                float av = (&a[rr].x)[j];
                acc[rr][0] += av * w0.x; acc[rr][1] += av * w0.y;
                acc[rr][2] += av * w0.z; acc[rr][3] += av * w0.w;
                acc[rr][4] += av * w1.x; acc[rr][5] += av * w1.y;
                acc[rr][6] += av * w1.z; acc[rr][7] += av * w1.w;
            }
        }
    }

    float4 bb0 = bs[c2], bb1 = bs[c2 + 1];
    #pragma unroll
    for (int rr = 0; rr < 4; rr++) {
        int r = row0 + rr;
        if (r >= n) break;
        float di = g_dinv[r];
        float s = di * di;
        // fp16 H: 8 cols -> 4 half2 -> one uint4 store
        __half2 p0 = __floats2half2_rn(acc[rr][0], acc[rr][1]);
        __half2 p1 = __floats2half2_rn(acc[rr][2], acc[rr][3]);
        __half2 p2 = __floats2half2_rn(acc[rr][4], acc[rr][5]);
        __half2 p3 = __floats2half2_rn(acc[rr][6], acc[rr][7]);
        uint4 hv;
        hv.x = reinterpret_cast<unsigned&>(p0);
        hv.y = reinterpret_cast<unsigned&>(p1);
        hv.z = reinterpret_cast<unsigned&>(p2);
        hv.w = reinterpret_cast<unsigned&>(p3);
        ((uint4*)Hh)[(size_t)r * 8 + cslice] = hv;
        // fp32 OUT = acc*s + b
        float4* o4 = (float4*)(OUT + (size_t)r * D) + c2;
        o4[0] = make_float4(acc[rr][0] * s + bb0.x, acc[rr][1] * s + bb0.y,
                            acc[rr][2] * s + bb0.z, acc[rr][3] * s + bb0.w);
        o4[1] = make_float4(acc[rr][4] * s + bb1.x, acc[rr][5] * s + bb1.y,
                            acc[rr][6] * s + bb1.z, acc[rr][7] * s + bb1.w);
    }
}

// CSR gather (fp16 source): 8 lanes per dst node, lane l owns halves [l*8, l*8+8).
// out[node] += sum_e h[csr[e].s] * csr[e].nrm
__global__ void __launch_bounds__(256) k_gather(const __half* __restrict__ Hh,
                                                float* __restrict__ out, int n) {
    int t = blockIdx.x * blockDim.x + threadIdx.x;
    int node = t >> 3;
    if (node >= n) return;
    int l = t & 7;

    int start = __ldg(&g_rowp[node]);
    int cnt   = __ldg(&g_deg[node]);
    const Edge* ce = g_csr + start;
    float acc[8];
    #pragma unroll
    for (int c = 0; c < 8; c++) acc[c] = 0.0f;

    if (cnt > 0) {
        Edge nxt = ce[0];
        for (int j = 0; j < cnt; j++) {
            Edge cur = nxt;
            if (j + 1 < cnt) nxt = ce[j + 1];
            uint4 hv = ((const uint4*)Hh)[(size_t)cur.s * 8 + l];
            __half2 p0 = reinterpret_cast<__half2&>(hv.x);
            __half2 p1 = reinterpret_cast<__half2&>(hv.y);
            __half2 p2 = reinterpret_cast<__half2&>(hv.z);
            __half2 p3 = reinterpret_cast<__half2&>(hv.w);
            float2 f0 = __half22float2(p0), f1 = __half22float2(p1);
            float2 f2 = __half22float2(p2), f3 = __half22float2(p3);
            float nm = cur.nrm;
            acc[0] += f0.x * nm; acc[1] += f0.y * nm;
            acc[2] += f1.x * nm; acc[3] += f1.y * nm;
            acc[4] += f2.x * nm; acc[5] += f2.y * nm;
            acc[6] += f3.x * nm; acc[7] += f3.y * nm;
        }
        float4* o = (float4*)(out + (size_t)node * D + l * 8);
        float4 o0 = o[0], o1 = o[1];
        o[0] = make_float4(o0.x + acc[0], o0.y + acc[1], o0.z + acc[2], o0.w + acc[3]);
        o[1] = make_float4(o1.x + acc[4], o1.y + acc[5], o1.z + acc[6], o1.w + acc[7]);
    }
}

extern "C" void kernel_launch(void* const* d_in, const int* in_sizes, int n_in,
                              void* d_out, int out_size) {
    const float* x  = (const float*)d_in[0];
    const int*   ei = (const int*)d_in[1];   // int32 (JAX x64-disabled)
    const float* W0 = (const float*)d_in[2];
    const float* b0 = (const float*)d_in[3];
    const float* W1 = (const float*)d_in[4];
    const float* b1 = (const float*)d_in[5];
    const float* W2 = (const float*)d_in[6];
    const float* b2 = (const float*)d_in[7];
    float* out = (float*)d_out;

    int n = in_sizes[0] / D;
    int e = in_sizes[1] / 2;
    const int* src = ei;
    const int* dst = ei + e;

    __half* hh; float *t0, *t1;
    cudaGetSymbolAddress((void**)&hh, g_hh);
    cudaGetSymbolAddress((void**)&t0, g_t0);
    cudaGetSymbolAddress((void**)&t1, g_t1);

    const int TB = 256;
    int gb_n    = (n + TB - 1) / TB;
    int gb_e    = (e + TB - 1) / TB;
    int gb_gemm = (n + 127) / 128;
    int nb_scan = (n + SCAN_B - 1) / SCAN_B;
    long long nl = (long long)n * 8;
    int gb_ga   = (int)((nl + TB - 1) / TB);

    // CSR build (once per launch, reused by 3 layers)
    k_zero<<<gb_n, TB>>>(n);
    k_count_deg<<<gb_e, TB>>>(dst, e);
    k_dinv<<<gb_n, TB>>>(n);
    k_scan_block<<<nb_scan, SCAN_B>>>(n);
    k_scan_bsum<<<1, 1>>>(nb_scan);
    k_scan_add<<<gb_n, TB>>>(n);
    k_fill<<<gb_e, TB>>>(src, dst, e);

    // layer 0
    k_gemm_fused<false><<<gb_gemm, TB>>>(x, W0, b0, hh, t0, n);
    k_gather<<<gb_ga, TB>>>(hh, t0, n);
    // layer 1
    k_gemm_fused<true><<<gb_gemm, TB>>>(t0, W1, b1, hh, t1, n);
    k_gather<<<gb_ga, TB>>>(hh, t1, n);
    // layer 2
    k_gemm_fused<true><<<gb_gemm, TB>>>(t1, W2, b2, hh, out, n);
    k_gather<<<gb_ga, TB>>>(hh, out, n);
}